// round 6
// baseline (speedup 1.0000x reference)
#include <cuda_runtime.h>
#include <math.h>

#define NB 4
#define NC 20
#define NT 16
#define NX 32
#define NY 32
#define NZ 16
#define S0 (NT*NX*NY*NZ)

typedef unsigned long long ull;

__device__ __forceinline__ ull pack2(float a, float b){
    ull r; asm("mov.b64 %0, {%1,%2};" : "=l"(r) : "f"(a), "f"(b)); return r;
}
__device__ __forceinline__ void unpack2(ull v, float &a, float &b){
    asm("mov.b64 {%0,%1}, %2;" : "=f"(a), "=f"(b) : "l"(v));
}
__device__ __forceinline__ void fma2(ull &d, ull a, ull b){
    asm("fma.rn.f32x2 %0, %1, %2, %0;" : "+l"(d) : "l"(a), "l"(b));
}

struct Scratch {
    float oc1[1310720], t2[81920], oc2[81920], t3[5120], oc3[5120];
    float od2[81920], od1[1310720];
    float od0[20971520], x3[20971520], x1[20971520];
    double stats[40];
    float2 ss[20];
    float2 f1[5242880], f2[1310720], f3[655360];
    float2 f4[327680], f5[327680], f6[327680], f7[327680];
};
__device__ Scratch g_s;

// ------------------------- conv4d k=3 pad=1 ---------------------------------
template<int CIN,int TI,int XI,int YI,int ZI,int TO,int XO,int YO,int ZO,int STRIDE>
__global__ void conv4d_kernel(const float* __restrict__ in1, const float* __restrict__ in2,
                              const float* __restrict__ w, const float* __restrict__ bias,
                              float* __restrict__ out)
{
    const int SOo = TO*XO*YO*ZO, SIi = TI*XI*YI*ZI;
    __shared__ __align__(16) float sw[81*20];
    int idx = blockIdx.x*blockDim.x + threadIdx.x;
    bool active = idx < NB*SOo;
    int b=0,to=0,xo=0,yo=0,zo=0;
    if (active){
        int r = idx;
        zo=r%ZO; r/=ZO; yo=r%YO; r/=YO; xo=r%XO; r/=XO; to=r%TO; b=r/TO;
    }
    ull acc[10];
#pragma unroll
    for (int j=0;j<10;j++) acc[j]=0ULL;
    int t0=to*STRIDE-1, x0=xo*STRIDE-1, y0=yo*STRIDE-1, z0=zo*STRIDE-1;

    for (int i=0;i<CIN;i++){
        __syncthreads();
        for (int j=threadIdx.x;j<81*20;j+=blockDim.x){
            int tap=j/20, o=j-tap*20;
            sw[j] = w[(o*CIN+i)*81+tap];
        }
        __syncthreads();
        if (active){
            const float* inp = (i<NC) ? (in1+(size_t)(b*NC+i)*SIi)
                                      : (in2+(size_t)(b*NC+(i-NC))*SIi);
            for (int kt=0;kt<3;kt++){
                int t=t0+kt; if ((unsigned)t>=(unsigned)TI) continue;
                for (int kx=0;kx<3;kx++){
                    int xx=x0+kx; if ((unsigned)xx>=(unsigned)XI) continue;
                    for (int ky=0;ky<3;ky++){
                        int yy=y0+ky; if ((unsigned)yy>=(unsigned)YI) continue;
                        const float* row = inp + ((t*XI+xx)*YI+yy)*ZI;
                        int tb=((kt*3+kx)*3+ky)*3;
#pragma unroll
                        for (int kz=0;kz<3;kz++){
                            int zz=z0+kz; if ((unsigned)zz>=(unsigned)ZI) continue;
                            float v = row[zz];
                            ull v2 = pack2(v,v);
                            const ull* wv = (const ull*)&sw[(tb+kz)*20];
#pragma unroll
                            for (int j=0;j<10;j++) fma2(acc[j], v2, wv[j]);
                        }
                    }
                }
            }
        }
    }
    if (active){
        int sp = ((to*XO+xo)*YO+yo)*ZO+zo;
#pragma unroll
        for (int j=0;j<10;j++){
            float a0,a1; unpack2(acc[j],a0,a1);
            int o0=2*j;
            if (bias){ a0+=bias[o0]; a1+=bias[o0+1]; }
            out[(size_t)(b*NC+o0)*SOo+sp]   = a0;
            out[(size_t)(b*NC+o0+1)*SOo+sp] = a1;
        }
    }
}

// ---------------- deconv k=4 s=2 p=1, + bias + lrelu ------------------------
template<int CIN,int TI,int XI,int YI,int ZI>
__global__ void deconv4d_kernel(const float* __restrict__ in1, const float* __restrict__ in2,
                                const float* __restrict__ w, const float* __restrict__ bias,
                                float* __restrict__ out)
{
    const int TO=2*TI, XO=2*XI, YO=2*YI, ZO=2*ZI;
    const int SOo=TO*XO*YO*ZO, SIi=TI*XI*YI*ZI;
    __shared__ __align__(16) float sw[256*20];
    int idx = blockIdx.x*blockDim.x + threadIdx.x;
    bool active = idx < NB*SOo;
    int b=0,to=0,xo=0,yo=0,zo=0;
    if (active){
        int r=idx;
        zo=r%ZO; r/=ZO; yo=r%YO; r/=YO; xo=r%XO; r/=XO; to=r%TO; b=r/TO;
    }
    int qt[2]={0,0},kt[2]={0,0},qx[2]={0,0},kx[2]={0,0};
    int qy[2]={0,0},ky[2]={0,0},qz[2]={0,0},kz[2]={0,0};
    int nt=0,nx=0,ny=0,nz=0;
    if (active){
        for (int d=0;d<2;d++){
            int q,k;
            q=((to+1)>>1)-d; k=to+1-2*q; if(q>=0&&q<TI&&k>=0&&k<4){qt[nt]=q;kt[nt]=k;nt++;}
            q=((xo+1)>>1)-d; k=xo+1-2*q; if(q>=0&&q<XI&&k>=0&&k<4){qx[nx]=q;kx[nx]=k;nx++;}
            q=((yo+1)>>1)-d; k=yo+1-2*q; if(q>=0&&q<YI&&k>=0&&k<4){qy[ny]=q;ky[ny]=k;ny++;}
            q=((zo+1)>>1)-d; k=zo+1-2*q; if(q>=0&&q<ZI&&k>=0&&k<4){qz[nz]=q;kz[nz]=k;nz++;}
        }
    }
    ull acc[10];
#pragma unroll
    for (int j=0;j<10;j++) acc[j]=0ULL;

    for (int i=0;i<CIN;i++){
        __syncthreads();
        for (int j=threadIdx.x;j<256*20;j+=blockDim.x){
            int k=j/20, o=j-k*20;
            sw[j] = w[(i*20+o)*256+k];
        }
        __syncthreads();
        if (active){
            const float* inp = (i<NC) ? (in1+(size_t)(b*NC+i)*SIi)
                                      : (in2+(size_t)(b*NC+(i-NC))*SIi);
            for (int a0=0;a0<nt;a0++)
            for (int a1=0;a1<nx;a1++){
                const float* pl = inp + (qt[a0]*XI+qx[a1])*YI*ZI;
                int kb0=(kt[a0]*4+kx[a1])*4;
                for (int a2=0;a2<ny;a2++){
                    const float* row = pl + qy[a2]*ZI;
                    int kb1=(kb0+ky[a2])*4;
                    for (int a3=0;a3<nz;a3++){
                        float v = row[qz[a3]];
                        ull v2 = pack2(v,v);
                        const ull* wv = (const ull*)&sw[(kb1+kz[a3])*20];
#pragma unroll
                        for (int j=0;j<10;j++) fma2(acc[j], v2, wv[j]);
                    }
                }
            }
        }
    }
    if (active){
        int sp = ((to*XO+xo)*YO+yo)*ZO+zo;
#pragma unroll
        for (int j=0;j<10;j++){
            float a0,a1; unpack2(acc[j],a0,a1);
            int o0=2*j;
            a0+=bias[o0]; a1+=bias[o0+1];
            a0 = a0>=0.f? a0 : 0.1f*a0;
            a1 = a1>=0.f? a1 : 0.1f*a1;
            out[(size_t)(b*NC+o0)*SOo+sp]   = a0;
            out[(size_t)(b*NC+o0+1)*SOo+sp] = a1;
        }
    }
}

// --------------------------- BatchNorm --------------------------------------
__global__ void bnstats_kernel(const float* __restrict__ in, int S, double* __restrict__ stats)
{
    __shared__ double sh[512];
    int c = blockIdx.x;
    double s=0.0, q=0.0;
    for (int idx=threadIdx.x; idx<NB*S; idx+=blockDim.x){
        int b=idx/S, r=idx-b*S;
        float v = in[(size_t)(b*NC+c)*S + r];
        s += (double)v; q += (double)v*(double)v;
    }
    sh[threadIdx.x]=s; sh[256+threadIdx.x]=q;
    __syncthreads();
    for (int off=128; off>0; off>>=1){
        if (threadIdx.x<off){
            sh[threadIdx.x]+=sh[threadIdx.x+off];
            sh[256+threadIdx.x]+=sh[256+threadIdx.x+off];
        }
        __syncthreads();
    }
    if (threadIdx.x==0){ stats[2*c]=sh[0]; stats[2*c+1]=sh[256]; }
}

__global__ void bnfin_kernel(const double* __restrict__ stats, const float* __restrict__ g,
                             const float* __restrict__ b, float2* __restrict__ ss, double n)
{
    int c = threadIdx.x; if (c>=NC) return;
    double mean = stats[2*c]/n;
    double var  = stats[2*c+1]/n - mean*mean;
    float a = g[c] * (float)(1.0/sqrt(var+1e-5));
    ss[c] = make_float2(a, b[c] - (float)mean*a);
}

__global__ void bnapply_kernel(float* __restrict__ data, int S, const float2* __restrict__ ss)
{
    int idx = blockIdx.x*blockDim.x + threadIdx.x;
    if (idx >= NB*NC*S) return;
    int c = (idx/S)%NC;
    float2 t = ss[c];
    float v = data[idx]*t.x + t.y;
    data[idx] = v>=0.f? v : 0.1f*v;
}

// ----------------------- Spectral: forward DFT stages -----------------------
__global__ void zfwd_kernel(const float* __restrict__ x, float2* __restrict__ F)
{
    __shared__ float2 tw[64];
    for (int j=threadIdx.x;j<64;j+=blockDim.x){
        int k=j>>4, z=j&15; float s,c; sincospif(-(float)(k*z)/8.0f,&s,&c); tw[j]=make_float2(c,s);
    }
    __syncthreads();
    int idx = blockIdx.x*blockDim.x + threadIdx.x;
    const int N = NB*NC*NT*NX*NY;
    if (idx>=N) return;
    const float* row = x + (size_t)idx*NZ;
    float v[16];
#pragma unroll
    for (int z=0;z<16;z++) v[z]=row[z];
#pragma unroll
    for (int k=0;k<4;k++){
        float ar=0.f, ai=0.f;
#pragma unroll
        for (int z=0;z<16;z++){ float2 t=tw[k*16+z]; ar+=v[z]*t.x; ai+=v[z]*t.y; }
        F[(size_t)idx*4+k]=make_float2(ar,ai);
    }
}

__global__ void yfwd_kernel(const float2* __restrict__ A, float2* __restrict__ B)
{
    __shared__ float2 tw[256];
    for (int j=threadIdx.x;j<256;j+=blockDim.x){
        int k=j>>5, y=j&31; float s,c; sincospif(-(float)(k*y)/16.0f,&s,&c); tw[j]=make_float2(c,s);
    }
    __syncthreads();
    int idx = blockIdx.x*blockDim.x + threadIdx.x;
    const int N = NB*NC*NT*NX*8*4;
    if (idx>=N) return;
    int kz=idx&3, ky=(idx>>2)&7, r=idx>>5;
    const float2* base = A + (size_t)r*(NY*4) + kz;
    float ar=0.f, ai=0.f;
    for (int y=0;y<NY;y++){
        float2 f=base[y*4]; float2 t=tw[ky*32+y];
        ar += f.x*t.x - f.y*t.y;
        ai += f.x*t.y + f.y*t.x;
    }
    B[idx]=make_float2(ar,ai);
}

__global__ void xfwd_kernel(const float2* __restrict__ A, float2* __restrict__ B)
{
    __shared__ float2 tw[512];
    for (int j=threadIdx.x;j<512;j+=blockDim.x){
        int ki=j>>5, xx=j&31; int k = ki<8? ki : ki+16;
        float s,c; sincospif(-(float)(k*xx)/16.0f,&s,&c); tw[j]=make_float2(c,s);
    }
    __syncthreads();
    int idx = blockIdx.x*blockDim.x + threadIdx.x;
    const int N = NB*NC*NT*16*8*4;
    if (idx>=N) return;
    int kz=idx&3, ky=(idx>>2)&7, ki=(idx>>5)&15, r=idx>>9;
    const float2* base = A + (size_t)r*1024 + ky*4 + kz;
    float ar=0.f, ai=0.f;
    for (int xx=0;xx<NX;xx++){
        float2 f=base[xx*32]; float2 t=tw[ki*32+xx];
        ar += f.x*t.x - f.y*t.y;
        ai += f.x*t.y + f.y*t.x;
    }
    B[idx]=make_float2(ar,ai);
}

__global__ void tfwd_kernel(const float2* __restrict__ A, float2* __restrict__ B)
{
    __shared__ float2 tw[128];
    for (int j=threadIdx.x;j<128;j+=blockDim.x){
        int ki=j>>4, t=j&15; int k = ki<4? ki : ki+8;
        float s,c; sincospif(-(float)(k*t)/8.0f,&s,&c); tw[j]=make_float2(c,s);
    }
    __syncthreads();
    int idx = blockIdx.x*blockDim.x + threadIdx.x;
    const int N = NB*NC*4096;
    if (idx>=N) return;
    int m=idx&511, ki=(idx>>9)&7, r=idx>>12;
    const float2* base = A + (size_t)r*(16*512) + m;
    float ar=0.f, ai=0.f;
    for (int t=0;t<16;t++){
        float2 f=base[t*512]; float2 w=tw[ki*16+t];
        ar += f.x*w.x - f.y*w.y;
        ai += f.x*w.y + f.y*w.x;
    }
    B[idx]=make_float2(ar,ai);
}

__global__ void cfwd_kernel(const float2* __restrict__ A, float2* __restrict__ B)
{
    __shared__ float2 tw[400];
    for (int j=threadIdx.x;j<400;j+=blockDim.x){
        int kc=j/20, c=j-kc*20; float s,cc; sincospif(-(float)(kc*c)/10.0f,&s,&cc); tw[j]=make_float2(cc,s);
    }
    __syncthreads();
    int idx = blockIdx.x*blockDim.x + threadIdx.x;
    const int N = NB*NC*4096;
    if (idx>=N) return;
    int m = idx & 4095;
    int kc = (idx>>12) % 20;
    int b  = idx / (20*4096);
    const float2* base = A + (size_t)b*81920 + m;
    float ar=0.f, ai=0.f;
    for (int c=0;c<20;c++){
        float2 f=base[c*4096]; float2 w=tw[kc*20+c];
        ar += f.x*w.x - f.y*w.y;
        ai += f.x*w.y + f.y*w.x;
    }
    B[idx]=make_float2(ar,ai);
}

__global__ void bfwd_kernel(const float2* __restrict__ A, float2* __restrict__ B)
{
    __shared__ float2 tw[16];
    for (int j=threadIdx.x;j<16;j+=blockDim.x){
        int kb=j>>2, b=j&3; float s,c; sincospif(-(float)(kb*b)/2.0f,&s,&c); tw[j]=make_float2(c,s);
    }
    __syncthreads();
    int idx = blockIdx.x*blockDim.x + threadIdx.x;
    const int N = NB*NC*4096;
    if (idx>=N) return;
    int m = idx & 4095;
    int kc = (idx>>12) % 20;
    int kb = idx / 81920;
    const float2* base = A + (size_t)kc*4096 + m;
    float ar=0.f, ai=0.f;
    for (int b=0;b<4;b++){
        float2 f=base[(size_t)b*81920]; float2 w=tw[kb*4+b];
        ar += f.x*w.x - f.y*w.y;
        ai += f.x*w.y + f.y*w.x;
    }
    B[idx]=make_float2(ar,ai);
}

// einsum over channel-frequency i with corner-selected complex weights
__global__ void einsum_kernel(const float2* __restrict__ F6,
                              const float* __restrict__ sw1, const float* __restrict__ sw2,
                              const float* __restrict__ sw3, const float* __restrict__ sw4,
                              float2* __restrict__ F7)
{
    int idx = blockIdx.x*blockDim.x + threadIdx.x;
    const int N = NB*NC*4096;
    if (idx>=N) return;
    int m  = idx & 4095;
    int o  = (idx>>12) % 20;
    int kb = idx / 81920;
    int kz=m&3, ky=(m>>2)&7, kxi=(m>>5)&15, kti=(m>>9)&7;
    const float* W = (kti<4) ? ((kxi<8)? sw1 : sw3)
                             : ((kxi<8)? sw2 : sw4);
    // weight strides for (20,20,4,8,8,4,2)
    int wofs = ((kti&3)*512 + (kxi&7)*64 + ky*8 + kz*2) + o*2048;
    const float2* fb = F6 + (size_t)kb*81920 + m;
    float ar=0.f, ai=0.f;
    for (int i=0;i<20;i++){
        float2 f = fb[(size_t)i*4096];
        const float* wp = W + (size_t)i*40960 + wofs;
        float wr=wp[0], wi=wp[1];
        ar += f.x*wr - f.y*wi;
        ai += f.x*wi + f.y*wr;
    }
    F7[idx]=make_float2(ar,ai);
}

// ----------------------- Spectral: inverse stages ---------------------------
__global__ void tinv_kernel(const float2* __restrict__ A, float2* __restrict__ B)
{
    __shared__ float2 tw[128];
    for (int j=threadIdx.x;j<128;j+=blockDim.x){
        int ki=j>>4, t=j&15; int k = ki<4? ki : ki+8;
        float s,c; sincospif((float)(k*t)/8.0f,&s,&c); tw[j]=make_float2(c,s);
    }
    __syncthreads();
    int idx = blockIdx.x*blockDim.x + threadIdx.x;
    const int N = NB*NC*16*512;
    if (idx>=N) return;
    int m=idx&511, t=(idx>>9)&15, r=idx>>13;
    const float2* base = A + (size_t)r*4096 + m;
    float ar=0.f, ai=0.f;
    for (int ki=0;ki<8;ki++){
        float2 f=base[ki*512]; float2 w=tw[ki*16+t];
        ar += f.x*w.x - f.y*w.y;
        ai += f.x*w.y + f.y*w.x;
    }
    B[idx]=make_float2(ar,ai);
}

__global__ void xinv_kernel(const float2* __restrict__ A, float2* __restrict__ B)
{
    __shared__ float2 tw[512];
    for (int j=threadIdx.x;j<512;j+=blockDim.x){
        int ki=j>>5, xx=j&31; int k = ki<8? ki : ki+16;
        float s,c; sincospif((float)(k*xx)/16.0f,&s,&c); tw[j]=make_float2(c,s);
    }
    __syncthreads();
    int idx = blockIdx.x*blockDim.x + threadIdx.x;
    const int N = NB*NC*16*32*32;
    if (idx>=N) return;
    int j=idx&31, xx=(idx>>5)&31, t=(idx>>10)&15, r=idx>>14;
    const float2* base = A + (size_t)r*8192 + t*512 + j;
    float ar=0.f, ai=0.f;
    for (int ki=0;ki<16;ki++){
        float2 f=base[ki*32]; float2 w=tw[ki*32+xx];
        ar += f.x*w.x - f.y*w.y;
        ai += f.x*w.y + f.y*w.x;
    }
    B[idx]=make_float2(ar,ai);
}

__global__ void yinv_kernel(const float2* __restrict__ A, float2* __restrict__ B)
{
    __shared__ float2 tw[256];
    for (int j=threadIdx.x;j<256;j+=blockDim.x){
        int k=j>>5, y=j&31; float s,c; sincospif((float)(k*y)/16.0f,&s,&c); tw[j]=make_float2(c,s);
    }
    __syncthreads();
    int idx = blockIdx.x*blockDim.x + threadIdx.x;
    const int N = NB*NC*16*32*32*4;
    if (idx>=N) return;
    int kz=idx&3, y=(idx>>2)&31, r=idx>>7;
    // input layout [r=(b,c,t,x)][ky*4+kz], stride 32 per r  (R4 bug: used r*128)
    const float2* base = A + (size_t)r*32 + kz;
    float ar=0.f, ai=0.f;
    for (int ky=0;ky<8;ky++){
        float2 f=base[ky*4]; float2 w=tw[ky*32+y];
        ar += f.x*w.x - f.y*w.y;
        ai += f.x*w.y + f.y*w.x;
    }
    B[idx]=make_float2(ar,ai);
}

__global__ void zinv_kernel(const float2* __restrict__ A, float* __restrict__ out)
{
    __shared__ float2 tw[64];
    for (int j=threadIdx.x;j<64;j+=blockDim.x){
        int k=j>>4, z=j&15; float s,c; sincospif((float)(k*z)/8.0f,&s,&c); tw[j]=make_float2(c,s);
    }
    __syncthreads();
    int idx = blockIdx.x*blockDim.x + threadIdx.x;
    const int N = NB*NC*S0;
    if (idx>=N) return;
    int z=idx&15, r=idx>>4;
    const float2* row = A + (size_t)r*4;
    float v = row[0].x;
#pragma unroll
    for (int k=1;k<4;k++){
        float2 f=row[k]; float2 w=tw[k*16+z];
        v += 2.f*(f.x*w.x - f.y*w.y);
    }
    out[idx] = v * (1.0f/262144.0f);
}

// --------------------- combine: relu(x1 + pointwise + x3) -------------------
__global__ void combine_kernel(const float* __restrict__ x, const float* __restrict__ x1,
                               const float* __restrict__ x3, const float* __restrict__ wpw,
                               const float* __restrict__ bpw, float* __restrict__ out)
{
    __shared__ float sw[400];
    __shared__ float sb[20];
    for (int j=threadIdx.x;j<400;j+=blockDim.x) sw[j]=wpw[j];
    for (int j=threadIdx.x;j<20;j+=blockDim.x) sb[j]=bpw[j];
    __syncthreads();
    int idx = blockIdx.x*blockDim.x+threadIdx.x;
    if (idx >= NB*S0) return;
    int b = idx / S0, sp = idx - b*S0;
    float xin[20];
#pragma unroll
    for (int i=0;i<20;i++) xin[i] = x[(size_t)(b*20+i)*S0+sp];
#pragma unroll 4
    for (int o=0;o<20;o++){
        float a = sb[o];
#pragma unroll
        for (int i=0;i<20;i++) a += sw[o*20+i]*xin[i];
        a += x1[(size_t)(b*20+o)*S0+sp] + x3[(size_t)(b*20+o)*S0+sp];
        out[(size_t)(b*20+o)*S0+sp] = a>=0.f? a : 0.f;
    }
}

// ---------------------------------------------------------------------------
extern "C" void kernel_launch(void* const* d_in, const int* in_sizes, int n_in,
                              void* d_out, int out_size)
{
    const float* x    = (const float*)d_in[0];
    const float* sw1  = (const float*)d_in[1];
    const float* sw2  = (const float*)d_in[2];
    const float* sw3  = (const float*)d_in[3];
    const float* sw4  = (const float*)d_in[4];
    const float* wpw  = (const float*)d_in[5];
    const float* bpw  = (const float*)d_in[6];
    const float* c1w  = (const float*)d_in[7];
    const float* c2w  = (const float*)d_in[8];
    const float* c21w = (const float*)d_in[9];
    const float* c3w  = (const float*)d_in[10];
    const float* c31w = (const float*)d_in[11];
    const float* bn1g = (const float*)d_in[12];
    const float* bn1b = (const float*)d_in[13];
    const float* bn2g = (const float*)d_in[14];
    const float* bn2b = (const float*)d_in[15];
    const float* bn21g= (const float*)d_in[16];
    const float* bn21b= (const float*)d_in[17];
    const float* bn3g = (const float*)d_in[18];
    const float* bn3b = (const float*)d_in[19];
    const float* bn31g= (const float*)d_in[20];
    const float* bn31b= (const float*)d_in[21];
    const float* d2w  = (const float*)d_in[22];
    const float* d2b  = (const float*)d_in[23];
    const float* d1w  = (const float*)d_in[24];
    const float* d1b  = (const float*)d_in[25];
    const float* d0w  = (const float*)d_in[26];
    const float* d0b  = (const float*)d_in[27];
    const float* outw = (const float*)d_in[28];
    const float* outb = (const float*)d_in[29];
    float* out = (float*)d_out;

    Scratch* s;
    cudaGetSymbolAddress((void**)&s, g_s);

    // ----- spectral branch -----
    {
        int n;
        n = NB*NC*NT*NX*NY;       zfwd_kernel<<<(n+255)/256,256>>>(x, s->f1);
        n = NB*NC*NT*NX*32;       yfwd_kernel<<<(n+255)/256,256>>>(s->f1, s->f2);
        n = NB*NC*NT*512;         xfwd_kernel<<<(n+255)/256,256>>>(s->f2, s->f3);
        n = NB*NC*4096;           tfwd_kernel<<<(n+255)/256,256>>>(s->f3, s->f4);
        n = NB*NC*4096;           cfwd_kernel<<<(n+255)/256,256>>>(s->f4, s->f5);
        n = NB*NC*4096;           bfwd_kernel<<<(n+255)/256,256>>>(s->f5, s->f6);
        n = NB*NC*4096;           einsum_kernel<<<(n+255)/256,256>>>(s->f6, sw1, sw2, sw3, sw4, s->f7);
        n = NB*NC*16*512;         tinv_kernel<<<(n+255)/256,256>>>(s->f7, s->f3);
        n = NB*NC*16*32*32;       xinv_kernel<<<(n+255)/256,256>>>(s->f3, s->f2);
        n = NB*NC*16*32*32*4;     yinv_kernel<<<(n+255)/256,256>>>(s->f2, s->f1);
        n = NB*NC*S0;             zinv_kernel<<<(n+255)/256,256>>>(s->f1, s->x1);
    }

    // ----- U-Net branch -----
    {
        int n;
        // c1: (16,32,32,16) -> (8,16,16,8), stride 2
        n = NB*16384;
        conv4d_kernel<20,16,32,32,16,8,16,16,8,2><<<(n+255)/256,256>>>(x,nullptr,c1w,nullptr,s->oc1);
        bnstats_kernel<<<20,256>>>(s->oc1,16384,s->stats);
        bnfin_kernel<<<1,32>>>(s->stats,bn1g,bn1b,s->ss,(double)(NB*16384));
        bnapply_kernel<<<(NB*20*16384+255)/256,256>>>(s->oc1,16384,s->ss);
        // c2: (8,16,16,8) -> (4,8,8,4), stride 2
        n = NB*1024;
        conv4d_kernel<20,8,16,16,8,4,8,8,4,2><<<(n+255)/256,256>>>(s->oc1,nullptr,c2w,nullptr,s->t2);
        bnstats_kernel<<<20,256>>>(s->t2,1024,s->stats);
        bnfin_kernel<<<1,32>>>(s->stats,bn2g,bn2b,s->ss,(double)(NB*1024));
        bnapply_kernel<<<(NB*20*1024+255)/256,256>>>(s->t2,1024,s->ss);
        // c21: (4,8,8,4) same, stride 1
        conv4d_kernel<20,4,8,8,4,4,8,8,4,1><<<(n+255)/256,256>>>(s->t2,nullptr,c21w,nullptr,s->oc2);
        bnstats_kernel<<<20,256>>>(s->oc2,1024,s->stats);
        bnfin_kernel<<<1,32>>>(s->stats,bn21g,bn21b,s->ss,(double)(NB*1024));
        bnapply_kernel<<<(NB*20*1024+255)/256,256>>>(s->oc2,1024,s->ss);
        // c3: (4,8,8,4) -> (2,4,4,2), stride 2
        n = NB*64;
        conv4d_kernel<20,4,8,8,4,2,4,4,2,2><<<(n+255)/256,256>>>(s->oc2,nullptr,c3w,nullptr,s->t3);
        bnstats_kernel<<<20,256>>>(s->t3,64,s->stats);
        bnfin_kernel<<<1,32>>>(s->stats,bn3g,bn3b,s->ss,(double)(NB*64));
        bnapply_kernel<<<(NB*20*64+255)/256,256>>>(s->t3,64,s->ss);
        // c31: (2,4,4,2) same, stride 1
        conv4d_kernel<20,2,4,4,2,2,4,4,2,1><<<(n+255)/256,256>>>(s->t3,nullptr,c31w,nullptr,s->oc3);
        bnstats_kernel<<<20,256>>>(s->oc3,64,s->stats);
        bnfin_kernel<<<1,32>>>(s->stats,bn31g,bn31b,s->ss,(double)(NB*64));
        bnapply_kernel<<<(NB*20*64+255)/256,256>>>(s->oc3,64,s->ss);
        // d2: (2,4,4,2) -> (4,8,8,4)
        n = NB*1024;
        deconv4d_kernel<20,2,4,4,2><<<(n+255)/256,256>>>(s->oc3,nullptr,d2w,d2b,s->od2);
        // d1: concat(oc2, od2), (4,8,8,4) -> (8,16,16,8)
        n = NB*16384;
        deconv4d_kernel<40,4,8,8,4><<<(n+255)/256,256>>>(s->oc2,s->od2,d1w,d1b,s->od1);
        // d0: concat(oc1, od1), (8,16,16,8) -> (16,32,32,16)
        n = NB*S0;
        deconv4d_kernel<40,8,16,16,8><<<(n+255)/256,256>>>(s->oc1,s->od1,d0w,d0b,s->od0);
        // out conv: concat(x, od0), k3 s1 p1, + bias
        conv4d_kernel<40,16,32,32,16,16,32,32,16,1><<<(n+255)/256,256>>>(x,s->od0,outw,outb,s->x3);
    }

    // ----- combine -----
    combine_kernel<<<(NB*S0+255)/256,256>>>(x, s->x1, s->x3, wpw, bpw, out);
}

// round 7
// speedup vs baseline: 1.7322x; 1.7322x over previous
#include <cuda_runtime.h>
#include <math.h>

#define NB 4
#define NC 20
#define NT 16
#define NX 32
#define NY 32
#define NZ 16
#define S0 (NT*NX*NY*NZ)

typedef unsigned long long ull;

__device__ __forceinline__ ull pack2(float a, float b){
    ull r; asm("mov.b64 %0, {%1,%2};" : "=l"(r) : "f"(a), "f"(b)); return r;
}
__device__ __forceinline__ void unpack2(ull v, float &a, float &b){
    asm("mov.b64 {%0,%1}, %2;" : "=f"(a), "=f"(b) : "l"(v));
}
__device__ __forceinline__ void fma2(ull &d, ull a, ull b){
    asm("fma.rn.f32x2 %0, %1, %2, %0;" : "+l"(d) : "l"(a), "l"(b));
}

struct Scratch {
    float oc1[1310720], t2[81920], oc2[81920], t3[5120], oc3[5120];
    float od2[81920], od1[1310720];
    float od0[20971520], x3[20971520], x1[20971520];
    double stats[40];
    float2 ss[20];
    float2 f1[5242880], f2[1310720], f3[655360];
    float2 f4[327680], f5[327680], f6[327680], f7[327680];
};
__device__ Scratch g_s;

// ------------------------- generic conv4d k=3 pad=1 (small layers) ----------
template<int CIN,int TI,int XI,int YI,int ZI,int TO,int XO,int YO,int ZO,int STRIDE>
__global__ void conv4d_kernel(const float* __restrict__ in1, const float* __restrict__ in2,
                              const float* __restrict__ w, const float* __restrict__ bias,
                              float* __restrict__ out)
{
    const int SOo = TO*XO*YO*ZO, SIi = TI*XI*YI*ZI;
    __shared__ __align__(16) float sw[81*20];
    int idx = blockIdx.x*blockDim.x + threadIdx.x;
    bool active = idx < NB*SOo;
    int b=0,to=0,xo=0,yo=0,zo=0;
    if (active){
        int r = idx;
        zo=r%ZO; r/=ZO; yo=r%YO; r/=YO; xo=r%XO; r/=XO; to=r%TO; b=r/TO;
    }
    ull acc[10];
#pragma unroll
    for (int j=0;j<10;j++) acc[j]=0ULL;
    int t0=to*STRIDE-1, x0=xo*STRIDE-1, y0=yo*STRIDE-1, z0=zo*STRIDE-1;

    for (int i=0;i<CIN;i++){
        __syncthreads();
        for (int j=threadIdx.x;j<81*20;j+=blockDim.x){
            int tap=j/20, o=j-tap*20;
            sw[j] = w[(o*CIN+i)*81+tap];
        }
        __syncthreads();
        if (active){
            const float* inp = (i<NC) ? (in1+(size_t)(b*NC+i)*SIi)
                                      : (in2+(size_t)(b*NC+(i-NC))*SIi);
            for (int kt=0;kt<3;kt++){
                int t=t0+kt; if ((unsigned)t>=(unsigned)TI) continue;
                for (int kx=0;kx<3;kx++){
                    int xx=x0+kx; if ((unsigned)xx>=(unsigned)XI) continue;
                    for (int ky=0;ky<3;ky++){
                        int yy=y0+ky; if ((unsigned)yy>=(unsigned)YI) continue;
                        const float* row = inp + ((t*XI+xx)*YI+yy)*ZI;
                        int tb=((kt*3+kx)*3+ky)*3;
#pragma unroll
                        for (int kz=0;kz<3;kz++){
                            int zz=z0+kz; if ((unsigned)zz>=(unsigned)ZI) continue;
                            float v = row[zz];
                            ull v2 = pack2(v,v);
                            const ull* wv = (const ull*)&sw[(tb+kz)*20];
#pragma unroll
                            for (int j=0;j<10;j++) fma2(acc[j], v2, wv[j]);
                        }
                    }
                }
            }
        }
    }
    if (active){
        int sp = ((to*XO+xo)*YO+yo)*ZO+zo;
#pragma unroll
        for (int j=0;j<10;j++){
            float a0,a1; unpack2(acc[j],a0,a1);
            int o0=2*j;
            if (bias){ a0+=bias[o0]; a1+=bias[o0+1]; }
            out[(size_t)(b*NC+o0)*SOo+sp]   = a0;
            out[(size_t)(b*NC+o0+1)*SOo+sp] = a1;
        }
    }
}

// --------- blocked out-conv: k=3 s=1 p=1, CIN=40, dims 16/32/32/16 ----------
// 2 output voxels per thread along z; weight vectors staged to registers.
__global__ __launch_bounds__(256,2)
void outconv_kernel(const float* __restrict__ in1, const float* __restrict__ in2,
                    const float* __restrict__ w, const float* __restrict__ bias,
                    float* __restrict__ out)
{
    const int SI = S0;
    __shared__ __align__(16) float sw[81*20];
    int idx = blockIdx.x*256 + threadIdx.x;      // 524288 threads exactly
    int zh = idx & 7;            // z pair index: outputs 2*zh, 2*zh+1
    int yo = (idx>>3) & 31;
    int xo = (idx>>8) & 31;
    int to = (idx>>13) & 15;
    int b  = idx>>17;
    int z0 = 2*zh;

    ull acc[2][10];
#pragma unroll
    for (int v=0;v<2;v++)
#pragma unroll
        for (int j=0;j<10;j++) acc[v][j]=0ULL;

    for (int i=0;i<40;i++){
        __syncthreads();
        for (int j=threadIdx.x;j<1620;j+=256){
            int tap=j/20, o=j-tap*20;
            sw[j] = w[(o*40+i)*81+tap];
        }
        __syncthreads();
        const float* inp = (i<20) ? (in1+(size_t)(b*20+i)*SI)
                                  : (in2+(size_t)(b*20+(i-20))*SI);
        for (int kt=0;kt<3;kt++){
            int t=to-1+kt; if ((unsigned)t>=16u) continue;
            for (int kx=0;kx<3;kx++){
                int xx=xo-1+kx; if ((unsigned)xx>=32u) continue;
                for (int ky=0;ky<3;ky++){
                    int yy=yo-1+ky; if ((unsigned)yy>=32u) continue;
                    const float* row = inp + ((t*32+xx)*32+yy)*16 + z0;
                    float in4[4];
                    in4[0] = (zh>0) ? row[-1] : 0.f;
                    in4[1] = row[0];
                    in4[2] = row[1];
                    in4[3] = (zh<7) ? row[2] : 0.f;
                    int tb = ((kt*3+kx)*3+ky)*3;
#pragma unroll
                    for (int kz=0;kz<3;kz++){
                        const ull* wv = (const ull*)&sw[(tb+kz)*20];
                        ull wr[10];
#pragma unroll
                        for (int j=0;j<10;j++) wr[j]=wv[j];
                        ull a2 = pack2(in4[kz],   in4[kz]);
                        ull b2 = pack2(in4[kz+1], in4[kz+1]);
#pragma unroll
                        for (int j=0;j<10;j++) fma2(acc[0][j], a2, wr[j]);
#pragma unroll
                        for (int j=0;j<10;j++) fma2(acc[1][j], b2, wr[j]);
                    }
                }
            }
        }
    }
    int sp = ((to*32+xo)*32+yo)*16 + z0;
#pragma unroll
    for (int v=0;v<2;v++)
#pragma unroll
    for (int j=0;j<10;j++){
        float a0,a1; unpack2(acc[v][j],a0,a1);
        int o0=2*j;
        a0+=bias[o0]; a1+=bias[o0+1];
        out[(size_t)(b*20+o0)*S0 + sp + v]   = a0;
        out[(size_t)(b*20+o0+1)*S0 + sp + v] = a1;
    }
}

// ------- generic deconv k=4 s=2 p=1 + bias + lrelu (small layers) -----------
template<int CIN,int TI,int XI,int YI,int ZI>
__global__ void deconv4d_kernel(const float* __restrict__ in1, const float* __restrict__ in2,
                                const float* __restrict__ w, const float* __restrict__ bias,
                                float* __restrict__ out)
{
    const int TO=2*TI, XO=2*XI, YO=2*YI, ZO=2*ZI;
    const int SOo=TO*XO*YO*ZO, SIi=TI*XI*YI*ZI;
    __shared__ __align__(16) float sw[256*20];
    int idx = blockIdx.x*blockDim.x + threadIdx.x;
    bool active = idx < NB*SOo;
    int b=0,to=0,xo=0,yo=0,zo=0;
    if (active){
        int r=idx;
        zo=r%ZO; r/=ZO; yo=r%YO; r/=YO; xo=r%XO; r/=XO; to=r%TO; b=r/TO;
    }
    int qt[2]={0,0},kt[2]={0,0},qx[2]={0,0},kx[2]={0,0};
    int qy[2]={0,0},ky[2]={0,0},qz[2]={0,0},kz[2]={0,0};
    int nt=0,nx=0,ny=0,nz=0;
    if (active){
        for (int d=0;d<2;d++){
            int q,k;
            q=((to+1)>>1)-d; k=to+1-2*q; if(q>=0&&q<TI&&k>=0&&k<4){qt[nt]=q;kt[nt]=k;nt++;}
            q=((xo+1)>>1)-d; k=xo+1-2*q; if(q>=0&&q<XI&&k>=0&&k<4){qx[nx]=q;kx[nx]=k;nx++;}
            q=((yo+1)>>1)-d; k=yo+1-2*q; if(q>=0&&q<YI&&k>=0&&k<4){qy[ny]=q;ky[ny]=k;ny++;}
            q=((zo+1)>>1)-d; k=zo+1-2*q; if(q>=0&&q<ZI&&k>=0&&k<4){qz[nz]=q;kz[nz]=k;nz++;}
        }
    }
    ull acc[10];
#pragma unroll
    for (int j=0;j<10;j++) acc[j]=0ULL;

    for (int i=0;i<CIN;i++){
        __syncthreads();
        for (int j=threadIdx.x;j<256*20;j+=blockDim.x){
            int k=j/20, o=j-k*20;
            sw[j] = w[(i*20+o)*256+k];
        }
        __syncthreads();
        if (active){
            const float* inp = (i<NC) ? (in1+(size_t)(b*NC+i)*SIi)
                                      : (in2+(size_t)(b*NC+(i-NC))*SIi);
            for (int a0=0;a0<nt;a0++)
            for (int a1=0;a1<nx;a1++){
                const float* pl = inp + (qt[a0]*XI+qx[a1])*YI*ZI;
                int kb0=(kt[a0]*4+kx[a1])*4;
                for (int a2=0;a2<ny;a2++){
                    const float* row = pl + qy[a2]*ZI;
                    int kb1=(kb0+ky[a2])*4;
                    for (int a3=0;a3<nz;a3++){
                        float v = row[qz[a3]];
                        ull v2 = pack2(v,v);
                        const ull* wv = (const ull*)&sw[(kb1+kz[a3])*20];
#pragma unroll
                        for (int j=0;j<10;j++) fma2(acc[j], v2, wv[j]);
                    }
                }
            }
        }
    }
    if (active){
        int sp = ((to*XO+xo)*YO+yo)*ZO+zo;
#pragma unroll
        for (int j=0;j<10;j++){
            float a0,a1; unpack2(acc[j],a0,a1);
            int o0=2*j;
            a0+=bias[o0]; a1+=bias[o0+1];
            a0 = a0>=0.f? a0 : 0.1f*a0;
            a1 = a1>=0.f? a1 : 0.1f*a1;
            out[(size_t)(b*NC+o0)*SOo+sp]   = a0;
            out[(size_t)(b*NC+o0+1)*SOo+sp] = a1;
        }
    }
}

// ------- blocked deconv: 2 outputs per thread at zo, zo+2 (share k taps) ----
// Requires ZO >= 8 (used for d1 and d0).
template<int CIN,int TI,int XI,int YI,int ZI>
__global__ __launch_bounds__(256,2)
void deconv4d_blk_kernel(const float* __restrict__ in1, const float* __restrict__ in2,
                         const float* __restrict__ w, const float* __restrict__ bias,
                         float* __restrict__ out)
{
    const int TO=2*TI, XO=2*XI, YO=2*YI, ZO=2*ZI;
    const int SOo=TO*XO*YO*ZO, SIi=TI*XI*YI*ZI;
    const int WZN = ZO/2;                 // (p, jh) combos
    __shared__ __align__(16) float sw[256*20];
    int idx = blockIdx.x*256 + threadIdx.x;   // NB*TO*XO*YO*WZN threads exactly
    int wz = idx % WZN;
    int r  = idx / WZN;
    int yo = r % YO; r /= YO;
    int xo = r % XO; r /= XO;
    int to = r % TO; int b = r / TO;
    int p  = wz & 1;
    int jh = wz >> 1;
    // outputs: zo = p + 4*jh + 2*v, v in {0,1}
    // inputs:  q = q0 + e, e=0..2, q0 = 2*jh - 1 + p
    // taps:    kA = 1-p uses e=v+1 ;  kB = 3-p uses e=v
    int q0 = 2*jh - 1 + p;
    int kA = 1-p, kB = 3-p;

    int qt[2]={0,0},kt[2]={0,0},qx[2]={0,0},kx[2]={0,0};
    int qy[2]={0,0},ky[2]={0,0};
    int nt=0,nx=0,ny=0;
    for (int d=0;d<2;d++){
        int q,k;
        q=((to+1)>>1)-d; k=to+1-2*q; if(q>=0&&q<TI){qt[nt]=q;kt[nt]=k;nt++;}
        q=((xo+1)>>1)-d; k=xo+1-2*q; if(q>=0&&q<XI){qx[nx]=q;kx[nx]=k;nx++;}
        q=((yo+1)>>1)-d; k=yo+1-2*q; if(q>=0&&q<YI){qy[ny]=q;ky[ny]=k;ny++;}
    }

    ull acc[2][10];
#pragma unroll
    for (int v=0;v<2;v++)
#pragma unroll
        for (int j=0;j<10;j++) acc[v][j]=0ULL;

    for (int i=0;i<CIN;i++){
        __syncthreads();
        for (int j=threadIdx.x;j<256*20;j+=256){
            int k=j/20, o=j-k*20;
            sw[j] = w[(i*20+o)*256+k];
        }
        __syncthreads();
        const float* inp = (i<NC) ? (in1+(size_t)(b*NC+i)*SIi)
                                  : (in2+(size_t)(b*NC+(i-NC))*SIi);
        for (int a0=0;a0<nt;a0++)
        for (int a1=0;a1<nx;a1++){
            const float* pl = inp + (qt[a0]*XI+qx[a1])*YI*ZI;
            int kb0=(kt[a0]*4+kx[a1])*4;
            for (int a2=0;a2<ny;a2++){
                const float* row = pl + qy[a2]*ZI;
                int kb1=(kb0+ky[a2])*4;
                float in3[3];
#pragma unroll
                for (int e=0;e<3;e++){
                    int q = q0+e;
                    in3[e] = ((unsigned)q < (unsigned)ZI) ? row[q] : 0.f;
                }
                {   // kz = kA, inputs e = v+1
                    const ull* wv = (const ull*)&sw[(kb1+kA)*20];
                    ull wr[10];
#pragma unroll
                    for (int j=0;j<10;j++) wr[j]=wv[j];
                    ull a2v = pack2(in3[1],in3[1]);
                    ull b2v = pack2(in3[2],in3[2]);
#pragma unroll
                    for (int j=0;j<10;j++) fma2(acc[0][j], a2v, wr[j]);
#pragma unroll
                    for (int j=0;j<10;j++) fma2(acc[1][j], b2v, wr[j]);
                }
                {   // kz = kB, inputs e = v
                    const ull* wv = (const ull*)&sw[(kb1+kB)*20];
                    ull wr[10];
#pragma unroll
                    for (int j=0;j<10;j++) wr[j]=wv[j];
                    ull a2v = pack2(in3[0],in3[0]);
                    ull b2v = pack2(in3[1],in3[1]);
#pragma unroll
                    for (int j=0;j<10;j++) fma2(acc[0][j], a2v, wr[j]);
#pragma unroll
                    for (int j=0;j<10;j++) fma2(acc[1][j], b2v, wr[j]);
                }
            }
        }
    }
    int spb = ((to*XO+xo)*YO+yo)*ZO + p + 4*jh;
#pragma unroll
    for (int v=0;v<2;v++)
#pragma unroll
    for (int j=0;j<10;j++){
        float a0,a1; unpack2(acc[v][j],a0,a1);
        int o0=2*j;
        a0+=bias[o0]; a1+=bias[o0+1];
        a0 = a0>=0.f? a0 : 0.1f*a0;
        a1 = a1>=0.f? a1 : 0.1f*a1;
        out[(size_t)(b*NC+o0)*SOo + spb + 2*v]   = a0;
        out[(size_t)(b*NC+o0+1)*SOo + spb + 2*v] = a1;
    }
}

// --------------------------- BatchNorm --------------------------------------
__global__ void bnstats_kernel(const float* __restrict__ in, int S, double* __restrict__ stats)
{
    __shared__ double sh[512];
    int c = blockIdx.x;
    double s=0.0, q=0.0;
    for (int idx=threadIdx.x; idx<NB*S; idx+=blockDim.x){
        int b=idx/S, r=idx-b*S;
        float v = in[(size_t)(b*NC+c)*S + r];
        s += (double)v; q += (double)v*(double)v;
    }
    sh[threadIdx.x]=s; sh[256+threadIdx.x]=q;
    __syncthreads();
    for (int off=128; off>0; off>>=1){
        if (threadIdx.x<off){
            sh[threadIdx.x]+=sh[threadIdx.x+off];
            sh[256+threadIdx.x]+=sh[256+threadIdx.x+off];
        }
        __syncthreads();
    }
    if (threadIdx.x==0){ stats[2*c]=sh[0]; stats[2*c+1]=sh[256]; }
}

__global__ void bnfin_kernel(const double* __restrict__ stats, const float* __restrict__ g,
                             const float* __restrict__ b, float2* __restrict__ ss, double n)
{
    int c = threadIdx.x; if (c>=NC) return;
    double mean = stats[2*c]/n;
    double var  = stats[2*c+1]/n - mean*mean;
    float a = g[c] * (float)(1.0/sqrt(var+1e-5));
    ss[c] = make_float2(a, b[c] - (float)mean*a);
}

__global__ void bnapply_kernel(float* __restrict__ data, int S, const float2* __restrict__ ss)
{
    int idx = blockIdx.x*blockDim.x + threadIdx.x;
    if (idx >= NB*NC*S) return;
    int c = (idx/S)%NC;
    float2 t = ss[c];
    float v = data[idx]*t.x + t.y;
    data[idx] = v>=0.f? v : 0.1f*v;
}

// ----------------------- Spectral: forward DFT stages -----------------------
__global__ void zfwd_kernel(const float* __restrict__ x, float2* __restrict__ F)
{
    __shared__ float2 tw[64];
    for (int j=threadIdx.x;j<64;j+=blockDim.x){
        int k=j>>4, z=j&15; float s,c; sincospif(-(float)(k*z)/8.0f,&s,&c); tw[j]=make_float2(c,s);
    }
    __syncthreads();
    int idx = blockIdx.x*blockDim.x + threadIdx.x;
    const int N = NB*NC*NT*NX*NY;
    if (idx>=N) return;
    const float* row = x + (size_t)idx*NZ;
    float v[16];
#pragma unroll
    for (int z=0;z<16;z++) v[z]=row[z];
#pragma unroll
    for (int k=0;k<4;k++){
        float ar=0.f, ai=0.f;
#pragma unroll
        for (int z=0;z<16;z++){ float2 t=tw[k*16+z]; ar+=v[z]*t.x; ai+=v[z]*t.y; }
        F[(size_t)idx*4+k]=make_float2(ar,ai);
    }
}

__global__ void yfwd_kernel(const float2* __restrict__ A, float2* __restrict__ B)
{
    __shared__ float2 tw[256];
    for (int j=threadIdx.x;j<256;j+=blockDim.x){
        int k=j>>5, y=j&31; float s,c; sincospif(-(float)(k*y)/16.0f,&s,&c); tw[j]=make_float2(c,s);
    }
    __syncthreads();
    int idx = blockIdx.x*blockDim.x + threadIdx.x;
    const int N = NB*NC*NT*NX*8*4;
    if (idx>=N) return;
    int kz=idx&3, ky=(idx>>2)&7, r=idx>>5;
    const float2* base = A + (size_t)r*(NY*4) + kz;
    float ar=0.f, ai=0.f;
    for (int y=0;y<NY;y++){
        float2 f=base[y*4]; float2 t=tw[ky*32+y];
        ar += f.x*t.x - f.y*t.y;
        ai += f.x*t.y + f.y*t.x;
    }
    B[idx]=make_float2(ar,ai);
}

__global__ void xfwd_kernel(const float2* __restrict__ A, float2* __restrict__ B)
{
    __shared__ float2 tw[512];
    for (int j=threadIdx.x;j<512;j+=blockDim.x){
        int ki=j>>5, xx=j&31; int k = ki<8? ki : ki+16;
        float s,c; sincospif(-(float)(k*xx)/16.0f,&s,&c); tw[j]=make_float2(c,s);
    }
    __syncthreads();
    int idx = blockIdx.x*blockDim.x + threadIdx.x;
    const int N = NB*NC*NT*16*8*4;
    if (idx>=N) return;
    int kz=idx&3, ky=(idx>>2)&7, ki=(idx>>5)&15, r=idx>>9;
    const float2* base = A + (size_t)r*1024 + ky*4 + kz;
    float ar=0.f, ai=0.f;
    for (int xx=0;xx<NX;xx++){
        float2 f=base[xx*32]; float2 t=tw[ki*32+xx];
        ar += f.x*t.x - f.y*t.y;
        ai += f.x*t.y + f.y*t.x;
    }
    B[idx]=make_float2(ar,ai);
}

__global__ void tfwd_kernel(const float2* __restrict__ A, float2* __restrict__ B)
{
    __shared__ float2 tw[128];
    for (int j=threadIdx.x;j<128;j+=blockDim.x){
        int ki=j>>4, t=j&15; int k = ki<4? ki : ki+8;
        float s,c; sincospif(-(float)(k*t)/8.0f,&s,&c); tw[j]=make_float2(c,s);
    }
    __syncthreads();
    int idx = blockIdx.x*blockDim.x + threadIdx.x;
    const int N = NB*NC*4096;
    if (idx>=N) return;
    int m=idx&511, ki=(idx>>9)&7, r=idx>>12;
    const float2* base = A + (size_t)r*(16*512) + m;
    float ar=0.f, ai=0.f;
    for (int t=0;t<16;t++){
        float2 f=base[t*512]; float2 w=tw[ki*16+t];
        ar += f.x*w.x - f.y*w.y;
        ai += f.x*w.y + f.y*w.x;
    }
    B[idx]=make_float2(ar,ai);
}

__global__ void cfwd_kernel(const float2* __restrict__ A, float2* __restrict__ B)
{
    __shared__ float2 tw[400];
    for (int j=threadIdx.x;j<400;j+=blockDim.x){
        int kc=j/20, c=j-kc*20; float s,cc; sincospif(-(float)(kc*c)/10.0f,&s,&cc); tw[j]=make_float2(cc,s);
    }
    __syncthreads();
    int idx = blockIdx.x*blockDim.x + threadIdx.x;
    const int N = NB*NC*4096;
    if (idx>=N) return;
    int m = idx & 4095;
    int kc = (idx>>12) % 20;
    int b  = idx / (20*4096);
    const float2* base = A + (size_t)b*81920 + m;
    float ar=0.f, ai=0.f;
    for (int c=0;c<20;c++){
        float2 f=base[c*4096]; float2 w=tw[kc*20+c];
        ar += f.x*w.x - f.y*w.y;
        ai += f.x*w.y + f.y*w.x;
    }
    B[idx]=make_float2(ar,ai);
}

__global__ void bfwd_kernel(const float2* __restrict__ A, float2* __restrict__ B)
{
    __shared__ float2 tw[16];
    for (int j=threadIdx.x;j<16;j+=blockDim.x){
        int kb=j>>2, b=j&3; float s,c; sincospif(-(float)(kb*b)/2.0f,&s,&c); tw[j]=make_float2(c,s);
    }
    __syncthreads();
    int idx = blockIdx.x*blockDim.x + threadIdx.x;
    const int N = NB*NC*4096;
    if (idx>=N) return;
    int m = idx & 4095;
    int kc = (idx>>12) % 20;
    int kb = idx / 81920;
    const float2* base = A + (size_t)kc*4096 + m;
    float ar=0.f, ai=0.f;
    for (int b=0;b<4;b++){
        float2 f=base[(size_t)b*81920]; float2 w=tw[kb*4+b];
        ar += f.x*w.x - f.y*w.y;
        ai += f.x*w.y + f.y*w.x;
    }
    B[idx]=make_float2(ar,ai);
}

__global__ void einsum_kernel(const float2* __restrict__ F6,
                              const float* __restrict__ sw1, const float* __restrict__ sw2,
                              const float* __restrict__ sw3, const float* __restrict__ sw4,
                              float2* __restrict__ F7)
{
    int idx = blockIdx.x*blockDim.x + threadIdx.x;
    const int N = NB*NC*4096;
    if (idx>=N) return;
    int m  = idx & 4095;
    int o  = (idx>>12) % 20;
    int kb = idx / 81920;
    int kz=m&3, ky=(m>>2)&7, kxi=(m>>5)&15, kti=(m>>9)&7;
    const float* W = (kti<4) ? ((kxi<8)? sw1 : sw3)
                             : ((kxi<8)? sw2 : sw4);
    int wofs = ((kti&3)*512 + (kxi&7)*64 + ky*8 + kz*2) + o*2048;
    const float2* fb = F6 + (size_t)kb*81920 + m;
    float ar=0.f, ai=0.f;
    for (int i=0;i<20;i++){
        float2 f = fb[(size_t)i*4096];
        const float* wp = W + (size_t)i*40960 + wofs;
        float wr=wp[0], wi=wp[1];
        ar += f.x*wr - f.y*wi;
        ai += f.x*wi + f.y*wr;
    }
    F7[idx]=make_float2(ar,ai);
}

// ----------------------- Spectral: inverse stages ---------------------------
__global__ void tinv_kernel(const float2* __restrict__ A, float2* __restrict__ B)
{
    __shared__ float2 tw[128];
    for (int j=threadIdx.x;j<128;j+=blockDim.x){
        int ki=j>>4, t=j&15; int k = ki<4? ki : ki+8;
        float s,c; sincospif((float)(k*t)/8.0f,&s,&c); tw[j]=make_float2(c,s);
    }
    __syncthreads();
    int idx = blockIdx.x*blockDim.x + threadIdx.x;
    const int N = NB*NC*16*512;
    if (idx>=N) return;
    int m=idx&511, t=(idx>>9)&15, r=idx>>13;
    const float2* base = A + (size_t)r*4096 + m;
    float ar=0.f, ai=0.f;
    for (int ki=0;ki<8;ki++){
        float2 f=base[ki*512]; float2 w=tw[ki*16+t];
        ar += f.x*w.x - f.y*w.y;
        ai += f.x*w.y + f.y*w.x;
    }
    B[idx]=make_float2(ar,ai);
}

__global__ void xinv_kernel(const float2* __restrict__ A, float2* __restrict__ B)
{
    __shared__ float2 tw[512];
    for (int j=threadIdx.x;j<512;j+=blockDim.x){
        int ki=j>>5, xx=j&31; int k = ki<8? ki : ki+16;
        float s,c; sincospif((float)(k*xx)/16.0f,&s,&c); tw[j]=make_float2(c,s);
    }
    __syncthreads();
    int idx = blockIdx.x*blockDim.x + threadIdx.x;
    const int N = NB*NC*16*32*32;
    if (idx>=N) return;
    int j=idx&31, xx=(idx>>5)&31, t=(idx>>10)&15, r=idx>>14;
    const float2* base = A + (size_t)r*8192 + t*512 + j;
    float ar=0.f, ai=0.f;
    for (int ki=0;ki<16;ki++){
        float2 f=base[ki*32]; float2 w=tw[ki*32+xx];
        ar += f.x*w.x - f.y*w.y;
        ai += f.x*w.y + f.y*w.x;
    }
    B[idx]=make_float2(ar,ai);
}

__global__ void yinv_kernel(const float2* __restrict__ A, float2* __restrict__ B)
{
    __shared__ float2 tw[256];
    for (int j=threadIdx.x;j<256;j+=blockDim.x){
        int k=j>>5, y=j&31; float s,c; sincospif((float)(k*y)/16.0f,&s,&c); tw[j]=make_float2(c,s);
    }
    __syncthreads();
    int idx = blockIdx.x*blockDim.x + threadIdx.x;
    const int N = NB*NC*16*32*32*4;
    if (idx>=N) return;
    int kz=idx&3, y=(idx>>2)&31, r=idx>>7;
    const float2* base = A + (size_t)r*32 + kz;
    float ar=0.f, ai=0.f;
    for (int ky=0;ky<8;ky++){
        float2 f=base[ky*4]; float2 w=tw[ky*32+y];
        ar += f.x*w.x - f.y*w.y;
        ai += f.x*w.y + f.y*w.x;
    }
    B[idx]=make_float2(ar,ai);
}

__global__ void zinv_kernel(const float2* __restrict__ A, float* __restrict__ out)
{
    __shared__ float2 tw[64];
    for (int j=threadIdx.x;j<64;j+=blockDim.x){
        int k=j>>4, z=j&15; float s,c; sincospif((float)(k*z)/8.0f,&s,&c); tw[j]=make_float2(c,s);
    }
    __syncthreads();
    int idx = blockIdx.x*blockDim.x + threadIdx.x;
    const int N = NB*NC*S0;
    if (idx>=N) return;
    int z=idx&15, r=idx>>4;
    const float2* row = A + (size_t)r*4;
    float v = row[0].x;
#pragma unroll
    for (int k=1;k<4;k++){
        float2 f=row[k]; float2 w=tw[k*16+z];
        v += 2.f*(f.x*w.x - f.y*w.y);
    }
    out[idx] = v * (1.0f/262144.0f);
}

// --------------------- combine: relu(x1 + pointwise + x3) -------------------
__global__ void combine_kernel(const float* __restrict__ x, const float* __restrict__ x1,
                               const float* __restrict__ x3, const float* __restrict__ wpw,
                               const float* __restrict__ bpw, float* __restrict__ out)
{
    __shared__ float sw[400];
    __shared__ float sb[20];
    for (int j=threadIdx.x;j<400;j+=blockDim.x) sw[j]=wpw[j];
    for (int j=threadIdx.x;j<20;j+=blockDim.x) sb[j]=bpw[j];
    __syncthreads();
    int idx = blockIdx.x*blockDim.x+threadIdx.x;
    if (idx >= NB*S0) return;
    int b = idx / S0, sp = idx - b*S0;
    float xin[20];
#pragma unroll
    for (int i=0;i<20;i++) xin[i] = x[(size_t)(b*20+i)*S0+sp];
#pragma unroll 4
    for (int o=0;o<20;o++){
        float a = sb[o];
#pragma unroll
        for (int i=0;i<20;i++) a += sw[o*20+i]*xin[i];
        a += x1[(size_t)(b*20+o)*S0+sp] + x3[(size_t)(b*20+o)*S0+sp];
        out[(size_t)(b*20+o)*S0+sp] = a>=0.f? a : 0.f;
    }
}

// ---------------------------------------------------------------------------
extern "C" void kernel_launch(void* const* d_in, const int* in_sizes, int n_in,
                              void* d_out, int out_size)
{
    const float* x    = (const float*)d_in[0];
    const float* sw1  = (const float*)d_in[1];
    const float* sw2  = (const float*)d_in[2];
    const float* sw3  = (const float*)d_in[3];
    const float* sw4  = (const float*)d_in[4];
    const float* wpw  = (const float*)d_in[5];
    const float* bpw  = (const float*)d_in[6];
    const float* c1w  = (const float*)d_in[7];
    const float* c2w  = (const float*)d_in[8];
    const float* c21w = (const float*)d_in[9];
    const float* c3w  = (const float*)d_in[10];
    const float* c31w = (const float*)d_in[11];
    const float* bn1g = (const float*)d_in[12];
    const float* bn1b = (const float*)d_in[13];
    const float* bn2g = (const float*)d_in[14];
    const float* bn2b = (const float*)d_in[15];
    const float* bn21g= (const float*)d_in[16];
    const float* bn21b= (const float*)d_in[17];
    const float* bn3g = (const float*)d_in[18];
    const float* bn3b = (const float*)d_in[19];
    const float* bn31g= (const float*)d_in[20];
    const float* bn31b= (const float*)d_in[21];
    const float* d2w  = (const float*)d_in[22];
    const float* d2b  = (const float*)d_in[23];
    const float* d1w  = (const float*)d_in[24];
    const float* d1b  = (const float*)d_in[25];
    const float* d0w  = (const float*)d_in[26];
    const float* d0b  = (const float*)d_in[27];
    const float* outw = (const float*)d_in[28];
    const float* outb = (const float*)d_in[29];
    float* out = (float*)d_out;

    Scratch* s;
    cudaGetSymbolAddress((void**)&s, g_s);

    // ----- spectral branch -----
    {
        int n;
        n = NB*NC*NT*NX*NY;       zfwd_kernel<<<(n+255)/256,256>>>(x, s->f1);
        n = NB*NC*NT*NX*32;       yfwd_kernel<<<(n+255)/256,256>>>(s->f1, s->f2);
        n = NB*NC*NT*512;         xfwd_kernel<<<(n+255)/256,256>>>(s->f2, s->f3);
        n = NB*NC*4096;           tfwd_kernel<<<(n+255)/256,256>>>(s->f3, s->f4);
        n = NB*NC*4096;           cfwd_kernel<<<(n+255)/256,256>>>(s->f4, s->f5);
        n = NB*NC*4096;           bfwd_kernel<<<(n+255)/256,256>>>(s->f5, s->f6);
        n = NB*NC*4096;           einsum_kernel<<<(n+255)/256,256>>>(s->f6, sw1, sw2, sw3, sw4, s->f7);
        n = NB*NC*16*512;         tinv_kernel<<<(n+255)/256,256>>>(s->f7, s->f3);
        n = NB*NC*16*32*32;       xinv_kernel<<<(n+255)/256,256>>>(s->f3, s->f2);
        n = NB*NC*16*32*32*4;     yinv_kernel<<<(n+255)/256,256>>>(s->f2, s->f1);
        n = NB*NC*S0;             zinv_kernel<<<(n+255)/256,256>>>(s->f1, s->x1);
    }

    // ----- U-Net branch -----
    {
        int n;
        n = NB*16384;
        conv4d_kernel<20,16,32,32,16,8,16,16,8,2><<<(n+255)/256,256>>>(x,nullptr,c1w,nullptr,s->oc1);
        bnstats_kernel<<<20,256>>>(s->oc1,16384,s->stats);
        bnfin_kernel<<<1,32>>>(s->stats,bn1g,bn1b,s->ss,(double)(NB*16384));
        bnapply_kernel<<<(NB*20*16384+255)/256,256>>>(s->oc1,16384,s->ss);
        n = NB*1024;
        conv4d_kernel<20,8,16,16,8,4,8,8,4,2><<<(n+255)/256,256>>>(s->oc1,nullptr,c2w,nullptr,s->t2);
        bnstats_kernel<<<20,256>>>(s->t2,1024,s->stats);
        bnfin_kernel<<<1,32>>>(s->stats,bn2g,bn2b,s->ss,(double)(NB*1024));
        bnapply_kernel<<<(NB*20*1024+255)/256,256>>>(s->t2,1024,s->ss);
        conv4d_kernel<20,4,8,8,4,4,8,8,4,1><<<(n+255)/256,256>>>(s->t2,nullptr,c21w,nullptr,s->oc2);
        bnstats_kernel<<<20,256>>>(s->oc2,1024,s->stats);
        bnfin_kernel<<<1,32>>>(s->stats,bn21g,bn21b,s->ss,(double)(NB*1024));
        bnapply_kernel<<<(NB*20*1024+255)/256,256>>>(s->oc2,1024,s->ss);
        n = NB*64;
        conv4d_kernel<20,4,8,8,4,2,4,4,2,2><<<(n+255)/256,256>>>(s->oc2,nullptr,c3w,nullptr,s->t3);
        bnstats_kernel<<<20,256>>>(s->t3,64,s->stats);
        bnfin_kernel<<<1,32>>>(s->stats,bn3g,bn3b,s->ss,(double)(NB*64));
        bnapply_kernel<<<(NB*20*64+255)/256,256>>>(s->t3,64,s->ss);
        conv4d_kernel<20,2,4,4,2,2,4,4,2,1><<<(n+255)/256,256>>>(s->t3,nullptr,c31w,nullptr,s->oc3);
        bnstats_kernel<<<20,256>>>(s->oc3,64,s->stats);
        bnfin_kernel<<<1,32>>>(s->stats,bn31g,bn31b,s->ss,(double)(NB*64));
        bnapply_kernel<<<(NB*20*64+255)/256,256>>>(s->oc3,64,s->ss);
        // d2: (2,4,4,2) -> (4,8,8,4)  (ZO=4: generic kernel)
        n = NB*1024;
        deconv4d_kernel<20,2,4,4,2><<<(n+255)/256,256>>>(s->oc3,nullptr,d2w,d2b,s->od2);
        // d1: concat(oc2, od2), (4,8,8,4) -> (8,16,16,8)  (blocked, 2 out/thread)
        n = NB*8*16*16*4;   // 16384 threads
        deconv4d_blk_kernel<40,4,8,8,4><<<(n+255)/256,256>>>(s->oc2,s->od2,d1w,d1b,s->od1);
        // d0: concat(oc1, od1), (8,16,16,8) -> (16,32,32,16)  (blocked)
        n = NB*16*32*32*8;  // 524288 threads
        deconv4d_blk_kernel<40,8,16,16,8><<<(n+255)/256,256>>>(s->oc1,s->od1,d0w,d0b,s->od0);
        // out conv: concat(x, od0), k3 s1 p1 + bias  (blocked, 2 out/thread)
        n = NB*16*32*32*8;  // 524288 threads
        outconv_kernel<<<n/256,256>>>(x,s->od0,outw,outb,s->x3);
    }

    // ----- combine -----
    combine_kernel<<<(NB*S0+255)/256,256>>>(x, s->x1, s->x3, wpw, bpw, out);
}